// round 15
// baseline (speedup 1.0000x reference)
#include <cuda_runtime.h>
#include <cuda_fp16.h>
#include <math.h>
#include <stdint.h>

#define SDIM 2048
#define EDIM 2048
#define NH   16
#define NKV  4
#define DH   128
#define NHG  12
#define RDIM 32
#define NSYM 4
#define NOUT 3840
#define CQ   0
#define CK   2048
#define CV   2560
#define CRQ  3072
#define CRK  3456
#define KQ   192

static __device__ float g_pr[SDIM*NOUT];
static __device__ float g_rs[NH*SDIM];
static __device__ __half g_eh [(size_t)NH*SDIM*SDIM];
static __device__ __half g_xh [SDIM*EDIM];
static __device__ __half g_wh [(size_t)NOUT*EDIM];
static __device__ __half g_woh[(size_t)EDIM*EDIM];
static __device__ __half g_aoh[(size_t)SDIM*EDIM];
static __device__ __half g_qa [(size_t)NH*SDIM*KQ];
static __device__ __half g_kb [(size_t)NH*SDIM*KQ];
static __device__ __half g_vth[(size_t)NKV*DH*SDIM];

// ---------------- PTX helpers ----------------
__device__ __forceinline__ uint32_t smem_u32(const void* p) {
    uint32_t a;
    asm("{ .reg .u64 t; cvta.to.shared.u64 t, %1; cvt.u32.u64 %0, t; }" : "=r"(a) : "l"(p));
    return a;
}
__device__ __forceinline__ void cpa16(uint32_t d, const void* g) {
    asm volatile("cp.async.cg.shared.global [%0], [%1], 16;" :: "r"(d), "l"(g));
}
__device__ __forceinline__ void cp_commit() { asm volatile("cp.async.commit_group;" ::: "memory"); }
template<int N> __device__ __forceinline__ void cp_wait() {
    asm volatile("cp.async.wait_group %0;" :: "n"(N) : "memory");
}
__device__ __forceinline__ void ldm_x4(uint32_t& r0, uint32_t& r1, uint32_t& r2, uint32_t& r3,
                                       uint32_t addr) {
    asm volatile("ldmatrix.sync.aligned.m8n8.x4.shared.b16 {%0,%1,%2,%3}, [%4];"
                 : "=r"(r0), "=r"(r1), "=r"(r2), "=r"(r3) : "r"(addr));
}
__device__ __forceinline__ void mma_f16(float* d, const uint32_t* a, const uint32_t* b) {
    asm volatile("mma.sync.aligned.m16n8k16.row.col.f32.f16.f16.f32 "
                 "{%0,%1,%2,%3}, {%4,%5,%6,%7}, {%8,%9}, {%0,%1,%2,%3};"
                 : "+f"(d[0]), "+f"(d[1]), "+f"(d[2]), "+f"(d[3])
                 : "r"(a[0]), "r"(a[1]), "r"(a[2]), "r"(a[3]), "r"(b[0]), "r"(b[1]));
}
__device__ __forceinline__ void sbody1(const float* s, __half* dh, int i) {
    float2 v = ((const float2*)s)[i];
    __half h0 = __float2half_rn(v.x), h1 = __float2half_rn(v.y);
    ((uint32_t*)dh)[i] = (uint32_t)__half_as_ushort(h0)
                       | ((uint32_t)__half_as_ushort(h1) << 16);
}

// ---------------- merged split: x | Wq | Wk | Wv | Wrq | Wrk | Wo ----------
__global__ __launch_bounds__(256) void split_all(
    const float* __restrict__ x,  const float* __restrict__ wq,
    const float* __restrict__ wk, const float* __restrict__ wv,
    const float* __restrict__ wrq, const float* __restrict__ wrk,
    const float* __restrict__ wo)
{
    int i = blockIdx.x * 256 + threadIdx.x;
    const int E0 = 2097152, E1 = 4194304, E2 = 4718592, E3 = 5242880,
              E4 = 5636096, E5 = 6029312, E6 = 8126464;
    if      (i < E0) sbody1(x,   g_xh, i);
    else if (i < E1) sbody1(wq,  g_wh + (size_t)CQ  * EDIM, i - E0);
    else if (i < E2) sbody1(wk,  g_wh + (size_t)CK  * EDIM, i - E1);
    else if (i < E3) sbody1(wv,  g_wh + (size_t)CV  * EDIM, i - E2);
    else if (i < E4) sbody1(wrq, g_wh + (size_t)CRQ * EDIM, i - E3);
    else if (i < E5) sbody1(wrk, g_wh + (size_t)CRK * EDIM, i - E4);
    else if (i < E6) sbody1(wo,  g_woh, i - E5);
}

// ---------------- shared machinery ----------------
#define GEMM_PREAMBLE                                                           \
    extern __shared__ __align__(1024) char dsm[];                               \
    const uint32_t sb = smem_u32(dsm);                                          \
    const int tid = threadIdx.x;                                                \
    const int l = tid & 31, wid = tid >> 5;                                     \
    const int cch = tid & 7;                                                    \
    const int akh = (l >> 4);                                                   \
    const int bkh = (l >> 3) & 1;                                               \
    const int lsw = l & 7;

#define LOAD128(base, P, ld, step) do {                                         \
    const __half* G = (P) + (size_t)(step) * 64;                                \
    _Pragma("unroll")                                                           \
    for (int it = 0; it < 4; it++) {                                            \
        int row = (tid >> 3) + 32 * it;                                         \
        uint32_t sw = row * 128u + 16u * (cch ^ (row & 7));                     \
        cpa16((base) + sw, G + (size_t)row * (ld) + cch * 8);                   \
    } } while (0)

#define LOAD64(base, P, ld, step) do {                                          \
    const __half* G = (P) + (size_t)(step) * 64;                                \
    _Pragma("unroll")                                                           \
    for (int it = 0; it < 2; it++) {                                            \
        int row = (tid >> 3) + 32 * it;                                         \
        uint32_t sw = row * 128u + 16u * (cch ^ (row & 7));                     \
        cpa16((base) + sw, G + (size_t)row * (ld) + cch * 8);                   \
    } } while (0)

#define INNER_128(Ab, Bb)                                                       \
    _Pragma("unroll")                                                           \
    for (int kk = 0; kk < 4; kk++) {                                            \
        uint32_t af[4][4], bf[4][2];                                            \
        _Pragma("unroll")                                                       \
        for (int tm = 0; tm < 4; tm++)                                          \
            ldm_x4(af[tm][0], af[tm][1], af[tm][2], af[tm][3],                  \
                   (Ab) + (uint32_t)(ar + tm * 16) * 128u + 16u * (((kk << 1) + akh) ^ lsw)); \
        _Pragma("unroll")                                                       \
        for (int np = 0; np < 2; np++) {                                        \
            uint32_t r0, r1, r2, r3;                                            \
            ldm_x4(r0, r1, r2, r3,                                              \
                   (Bb) + (uint32_t)(br + np * 16) * 128u + 16u * (((kk << 1) + bkh) ^ lsw)); \
            bf[2*np][0] = r0; bf[2*np][1] = r1; bf[2*np+1][0] = r2; bf[2*np+1][1] = r3; \
        }                                                                       \
        _Pragma("unroll")                                                       \
        for (int tm = 0; tm < 4; tm++)                                          \
            _Pragma("unroll")                                                   \
            for (int tn = 0; tn < 4; tn++) mma_f16(acc[tm][tn], af[tm], bf[tn]); \
    }

// ---------------- single-product fp16 GEMM (proj / Wo) ----------------
// CTA 128x128, warp tile 32x64 (warp grid 4x2), mma:ldm ratio 2.67.
// Stage: A 16KB @0, B 16KB @16384; 2 stages, stride 32768 (64KB total).
__global__ __launch_bounds__(256, 3) void gemm1(
    const __half* __restrict__ Ah, const __half* __restrict__ Bh,
    float* __restrict__ C, int ldc, int K)
{
    GEMM_PREAMBLE
    const int wm = wid & 3, wn = wid >> 2;
    const int m0 = blockIdx.y << 7, n0 = blockIdx.x << 7;
    const int steps = K >> 6;
    const __half* Ah_ = Ah + (size_t)m0 * K;
    const __half* Bh_ = Bh + (size_t)n0 * K;

    float acc[2][8][4];
#pragma unroll
    for (int i = 0; i < 2; i++)
#pragma unroll
        for (int j = 0; j < 8; j++)
#pragma unroll
            for (int r = 0; r < 4; r++) acc[i][j][r] = 0.f;

    const int ar = wm * 32 + (l & 7) + (l & 8);
    const int br = wn * 64 + (l & 7) + 8 * (l >> 4);

    LOAD128(sb, Ah_, K, 0);
    LOAD128(sb + 16384u, Bh_, K, 0);
    cp_commit();

    for (int s = 0; s < steps; s++) {
        cp_wait<0>();
        __syncthreads();
        if (s + 1 < steps) {
            uint32_t b2 = sb + ((s + 1) & 1) * 32768u;
            LOAD128(b2, Ah_, K, s + 1);
            LOAD128(b2 + 16384u, Bh_, K, s + 1);
            cp_commit();
        }
        const uint32_t Ast = sb + (s & 1) * 32768u;
        const uint32_t Bst = Ast + 16384u;
#pragma unroll
        for (int kk = 0; kk < 4; kk++) {
            uint32_t af[2][4];
#pragma unroll
            for (int tm = 0; tm < 2; tm++)
                ldm_x4(af[tm][0], af[tm][1], af[tm][2], af[tm][3],
                       Ast + (uint32_t)(ar + tm * 16) * 128u + 16u * (((kk << 1) + akh) ^ lsw));
#pragma unroll
            for (int nh = 0; nh < 2; nh++) {
                uint32_t bf[4][2];
#pragma unroll
                for (int np = 0; np < 2; np++) {
                    uint32_t r0, r1, r2, r3;
                    ldm_x4(r0, r1, r2, r3,
                           Bst + (uint32_t)(br + nh * 32 + np * 16) * 128u
                              + 16u * (((kk << 1) + bkh) ^ lsw));
                    bf[2*np][0] = r0; bf[2*np][1] = r1;
                    bf[2*np+1][0] = r2; bf[2*np+1][1] = r3;
                }
#pragma unroll
                for (int tm = 0; tm < 2; tm++)
#pragma unroll
                    for (int j = 0; j < 4; j++)
                        mma_f16(acc[tm][nh * 4 + j], af[tm], bf[j]);
            }
        }
    }
    const int er = m0 + wm * 32 + (l >> 2);
    const int ec = n0 + wn * 64 + 2 * (l & 3);
#pragma unroll
    for (int tm = 0; tm < 2; tm++)
#pragma unroll
        for (int tn = 0; tn < 8; tn++) {
            float* p0 = C + (size_t)(er + tm * 16) * ldc + ec + tn * 8;
            float* p1 = C + (size_t)(er + tm * 16 + 8) * ldc + ec + tn * 8;
            *(float2*)p0 = make_float2(acc[tm][tn][0], acc[tm][tn][1]);
            *(float2*)p1 = make_float2(acc[tm][tn][2], acc[tm][tn][3]);
        }
}

// ---------------- scores: mma (KQ=192) + exp/16 -> fp16 + row-sum atomics ---
__global__ __launch_bounds__(256) void scores_mma()
{
    GEMM_PREAMBLE
    const int wm = wid & 1, wn = wid >> 1;
    const int h = blockIdx.y, idx = blockIdx.x;
    int ti = (int)((sqrtf(8.f * idx + 1.f) - 1.f) * 0.5f);
    while ((ti + 1) * (ti + 2) / 2 <= idx) ti++;
    while (ti * (ti + 1) / 2 > idx) ti--;
    const int tj = idx - ti * (ti + 1) / 2;
    const int i0 = ti << 7, j0 = tj << 7;
    const __half* Ab_ = g_qa + ((size_t)h * SDIM + i0) * KQ;
    const __half* Bb_ = g_kb + ((size_t)h * SDIM + j0) * KQ;
    const int steps = KQ >> 6;

    float acc[4][4][4];
#pragma unroll
    for (int i = 0; i < 4; i++)
#pragma unroll
        for (int j = 0; j < 4; j++)
#pragma unroll
            for (int r = 0; r < 4; r++) acc[i][j][r] = 0.f;
    const int ar = wm * 64 + (l & 7) + (l & 8);
    const int br = wn * 32 + (l & 7) + 8 * (l >> 4);

    LOAD128(sb, Ab_, KQ, 0); LOAD128(sb + 16384u, Bb_, KQ, 0); cp_commit();
    LOAD128(sb + 32768u, Ab_, KQ, 1); LOAD128(sb + 49152u, Bb_, KQ, 1); cp_commit();

    for (int s = 0; s < steps; s++) {
        cp_wait<1>();
        __syncthreads();
        if (s + 2 < steps) {
            uint32_t b2 = sb + ((s + 2) % 3) * 32768u;
            LOAD128(b2, Ab_, KQ, s + 2); LOAD128(b2 + 16384u, Bb_, KQ, s + 2);
        }
        cp_commit();
        const uint32_t Ab = sb + (s % 3) * 32768u;
        const uint32_t Bb = Ab + 16384u;
        INNER_128(Ab, Bb)
    }
    const int er = i0 + wm * 64 + (l >> 2);
    const int ec = j0 + wn * 32 + 2 * (l & 3);
    float rsum[4][2];
#pragma unroll
    for (int tm = 0; tm < 4; tm++) { rsum[tm][0] = 0.f; rsum[tm][1] = 0.f; }
#pragma unroll
    for (int tm = 0; tm < 4; tm++)
#pragma unroll
        for (int tn = 0; tn < 4; tn++) {
            int r0 = er + tm * 16, r1 = r0 + 8, c = ec + tn * 8;
            float e00 = (c     <= r0) ? __expf(acc[tm][tn][0]) * 0.0625f : 0.f;
            float e01 = (c + 1 <= r0) ? __expf(acc[tm][tn][1]) * 0.0625f : 0.f;
            float e10 = (c     <= r1) ? __expf(acc[tm][tn][2]) * 0.0625f : 0.f;
            float e11 = (c + 1 <= r1) ? __expf(acc[tm][tn][3]) * 0.0625f : 0.f;
            __half2 v0; v0.x = __float2half_rn(e00); v0.y = __float2half_rn(e01);
            __half2 v1; v1.x = __float2half_rn(e10); v1.y = __float2half_rn(e11);
            *(__half2*)(g_eh + ((size_t)h * SDIM + r0) * SDIM + c) = v0;
            *(__half2*)(g_eh + ((size_t)h * SDIM + r1) * SDIM + c) = v1;
            rsum[tm][0] += e00 + e01;
            rsum[tm][1] += e10 + e11;
        }
#pragma unroll
    for (int tm = 0; tm < 4; tm++)
#pragma unroll
        for (int rr = 0; rr < 2; rr++) {
            float v = rsum[tm][rr];
            v += __shfl_xor_sync(0xffffffffu, v, 1);
            v += __shfl_xor_sync(0xffffffffu, v, 2);
            if ((l & 3) == 0)
                atomicAdd(&g_rs[h * SDIM + er + tm * 16 + rr * 8], v);
        }
}

// ---------------- AV: single-product GEMM over eh, normalize at end ----------
__global__ __launch_bounds__(256) void av_mma()
{
    GEMM_PREAMBLE
    const int wm = wid & 1, wn = wid >> 1;
    const int h = blockIdx.y;
    const __half* Vh_ = g_vth + (size_t)(h >> 2) * DH * SDIM;

    const int ar = wm * 32 + (l & 7) + (l & 8);
    const int br = wn * 32 + (l & 7) + 8 * (l >> 4);

    for (int half = 0; half < 2; half++) {
        const int mt = half ? 31 - (int)blockIdx.x : (int)blockIdx.x;
        const int m0 = mt << 6;
        const int steps = mt + 1;
        const __half* Ae_ = g_eh + ((size_t)h * SDIM + m0) * SDIM;

        float acc[2][4][4];
#pragma unroll
        for (int i = 0; i < 2; i++)
#pragma unroll
            for (int j = 0; j < 4; j++)
#pragma unroll
                for (int r = 0; r < 4; r++) acc[i][j][r] = 0.f;

        LOAD64(sb, Ae_, SDIM, 0);
        LOAD128(sb + 8192u, Vh_, SDIM, 0);
        cp_commit();

        for (int s = 0; s < steps; s++) {
            cp_wait<0>();
            __syncthreads();
            if (s + 1 < steps) {
                uint32_t b2 = sb + ((s + 1) & 1) * 24576u;
                LOAD64(b2, Ae_, SDIM, s + 1);
                LOAD128(b2 + 8192u, Vh_, SDIM, s + 1);
                cp_commit();
            }
            const uint32_t Ast = sb + (s & 1) * 24576u;
            const uint32_t Bst = Ast + 8192u;
#pragma unroll
            for (int kk = 0; kk < 4; kk++) {
                uint32_t bf[4][2], af[2][4];
#pragma unroll
                for (int np = 0; np < 2; np++) {
                    uint32_t r0, r1, r2, r3;
                    ldm_x4(r0, r1, r2, r3,
                           Bst + (uint32_t)(br + np * 16) * 128u + 16u * (((kk << 1) + bkh) ^ lsw));
                    bf[2*np][0] = r0; bf[2*np][1] = r1; bf[2*np+1][0] = r2; bf[2*np+1][1] = r3;
                }
#pragma unroll
                for (int tm = 0; tm < 2; tm++)
                    ldm_x4(af[tm][0], af[tm][1], af[tm][2], af[tm][3],
                           Ast + (uint32_t)(ar + tm * 16) * 128u + 16u * (((kk << 1) + akh) ^ lsw));
#pragma unroll
                for (int tm = 0; tm < 2; tm++)
#pragma unroll
                    for (int tn = 0; tn < 4; tn++) mma_f16(acc[tm][tn], af[tm], bf[tn]);
            }
        }
        const int er = m0 + wm * 32 + (l >> 2);
        const int ecl = wn * 32 + 2 * (l & 3);
#pragma unroll
        for (int tm = 0; tm < 2; tm++) {
            float ir0 = 1.f / g_rs[h * SDIM + er + tm * 16];
            float ir1 = 1.f / g_rs[h * SDIM + er + tm * 16 + 8];
#pragma unroll
            for (int tn = 0; tn < 4; tn++) {
                int c = h * DH + ecl + tn * 8;
                int r0 = er + tm * 16, r1 = r0 + 8;
                __half h00 = __float2half_rn(acc[tm][tn][0] * ir0);
                __half h01 = __float2half_rn(acc[tm][tn][1] * ir0);
                __half h10 = __float2half_rn(acc[tm][tn][2] * ir1);
                __half h11 = __float2half_rn(acc[tm][tn][3] * ir1);
                ((uint32_t*)g_aoh)[(size_t)r0 * (EDIM/2) + (c >> 1)] =
                    (uint32_t)__half_as_ushort(h00) | ((uint32_t)__half_as_ushort(h01) << 16);
                ((uint32_t*)g_aoh)[(size_t)r1 * (EDIM/2) + (c >> 1)] =
                    (uint32_t)__half_as_ushort(h10) | ((uint32_t)__half_as_ushort(h11) << 16);
            }
        }
        __syncthreads();
    }
}

// ---------------- merged RMSNorm + RoPE fill: qa (y<16) / kb (y>=16) --------
__global__ __launch_bounds__(128) void norm_fill(
    const float* __restrict__ qw, const float* __restrict__ kw,
    const float* __restrict__ gscale)
{
    const int s = blockIdx.x, y = blockIdx.y, d = threadIdx.x;
    const bool isQ = (y < NH);
    const int hq = y, kvh = y - NH;
    const float* w = isQ ? qw : kw;
    const int col = isQ ? (CQ + hq * DH) : (CK + kvh * DH);
    float v = g_pr[(size_t)s * NOUT + col + d];
    float ss = v * v;
#pragma unroll
    for (int o = 16; o; o >>= 1) ss += __shfl_xor_sync(0xffffffffu, ss, o);
    __shared__ float r4[4];
    __shared__ float sh[DH];
    if ((d & 31) == 0) r4[d >> 5] = ss;
    __syncthreads();
    float nv = v * rsqrtf((r4[0]+r4[1]+r4[2]+r4[3]) * (1.f / DH) + 1e-6f) * w[d];
    sh[d] = nv;
    __syncthreads();
    const int dm = d & 63;
    float f = 1.f / powf(10000.f, (float)(2 * dm) * (1.f / DH));
    float cs, sn; sincosf((float)s * f, &sn, &cs);
    float rot = (d < 64) ? -sh[d + 64] : sh[d - 64];
    float rv = nv * cs + rot * sn;

    if (isQ) {
        __half* row = g_qa + ((size_t)hq * SDIM + s) * KQ;
        row[d] = __float2half_rn(rv * 0.08838834764831845f);
        if (d < 32) {
            float bv = 0.f;
            if (hq < NHG) bv = gscale[hq] * (hq < NSYM ? 0.5f : 1.f)
                             * g_pr[(size_t)s * NOUT + CRQ + hq * RDIM + d];
            row[128 + d] = __float2half_rn(bv);
        } else if (d < 64) {
            int r = d - 32;
            float bv = 0.f;
            if (hq < NSYM) bv = gscale[hq] * 0.5f * g_pr[(size_t)s * NOUT + CRK + hq * RDIM + r];
            row[160 + r] = __float2half_rn(bv);
        }
    } else {
        __half kh = __float2half_rn(rv);
#pragma unroll
        for (int e = 0; e < 4; e++) {
            int h = kvh * 4 + e;
            __half* row = g_kb + ((size_t)h * SDIM + s) * KQ;
            row[d] = kh;
            if (d < 32) {
                float bv = (h < NHG) ? g_pr[(size_t)s * NOUT + CRK + h * RDIM + d] : 0.f;
                row[128 + d] = __float2half_rn(bv);
            } else if (d < 64) {
                int r = d - 32;
                float bv = (h < NSYM) ? g_pr[(size_t)s * NOUT + CRQ + h * RDIM + r] : 0.f;
                row[160 + r] = __float2half_rn(bv);
            }
        }
    }
}

// ---------------- fill vth (smem transpose, fp16 single) ----------------
__global__ __launch_bounds__(128) void fill_vh()
{
    __shared__ float sm[64][129];
    const int jb = blockIdx.x, kvh = blockIdx.y;
    const int tid = threadIdx.x;
    for (int jj = 0; jj < 64; jj++)
        sm[jj][tid] = g_pr[(size_t)(jb * 64 + jj) * NOUT + CV + kvh * DH + tid];
    __syncthreads();
    const int w = tid >> 5, ln = tid & 31;
    for (int d = w; d < DH; d += 4) {
        __half h0 = __float2half_rn(sm[2*ln][d]);
        __half h1 = __float2half_rn(sm[2*ln+1][d]);
        uint32_t* oh = (uint32_t*)(g_vth + (size_t)(kvh * DH + d) * SDIM + jb * 64);
        oh[ln] = (uint32_t)__half_as_ushort(h0) | ((uint32_t)__half_as_ushort(h1) << 16);
    }
}

// ---------------- Host ----------------
extern "C" void kernel_launch(void* const* d_in, const int* in_sizes, int n_in,
                              void* d_out, int out_size)
{
    const float* x   = (const float*)d_in[0];
    const float* Wq  = (const float*)d_in[1];
    const float* Wk  = (const float*)d_in[2];
    const float* Wv  = (const float*)d_in[3];
    const float* Wo  = (const float*)d_in[4];
    const float* qnw = (const float*)d_in[5];
    const float* knw = (const float*)d_in[6];
    const float* Wrq = (const float*)d_in[7];
    const float* Wrk = (const float*)d_in[8];
    const float* gsc = (const float*)d_in[9];
    float* out = (float*)d_out;

    float *pr, *rs;
    __half *xh, *wh, *woh, *aoh;
    cudaGetSymbolAddress((void**)&pr,  g_pr);
    cudaGetSymbolAddress((void**)&rs,  g_rs);
    cudaGetSymbolAddress((void**)&xh,  g_xh);
    cudaGetSymbolAddress((void**)&wh,  g_wh);
    cudaGetSymbolAddress((void**)&woh, g_woh);
    cudaGetSymbolAddress((void**)&aoh, g_aoh);

    cudaFuncSetAttribute(gemm1,      cudaFuncAttributeMaxDynamicSharedMemorySize, 65536);
    cudaFuncSetAttribute(scores_mma, cudaFuncAttributeMaxDynamicSharedMemorySize, 98304);
    cudaFuncSetAttribute(av_mma,     cudaFuncAttributeMaxDynamicSharedMemorySize, 49152);

    split_all<<<31744, 256>>>(x, Wq, Wk, Wv, Wrq, Wrk, Wo);

    // merged projection GEMM (CTA 128x128, warp 32x64)
    gemm1<<<dim3(NOUT/128, SDIM/128), 256, 65536>>>(xh, wh, pr, NOUT, EDIM);

    cudaMemsetAsync(rs, 0, NH * SDIM * sizeof(float));

    norm_fill<<<dim3(SDIM, NH + NKV), 128>>>(qnw, knw, gsc);
    fill_vh<<<dim3(SDIM/64, NKV), 128>>>();

    scores_mma<<<dim3(136, NH), 256, 98304>>>();
    av_mma<<<dim3(16, NH), 256, 49152>>>();

    gemm1<<<dim3(EDIM/128, SDIM/128), 256, 65536>>>(aoh, woh, out, EDIM, EDIM);
}

// round 16
// speedup vs baseline: 1.4498x; 1.4498x over previous
#include <cuda_runtime.h>
#include <cuda_fp16.h>
#include <math.h>
#include <stdint.h>

#define SDIM 2048
#define EDIM 2048
#define NH   16
#define NKV  4
#define DH   128
#define NHG  12
#define RDIM 32
#define NSYM 4
#define NOUT 3840
#define CQ   0
#define CK   2048
#define CV   2560
#define CRQ  3072
#define CRK  3456
#define KQ   192

static __device__ float g_pr[SDIM*NOUT];
static __device__ float g_rs[NH*SDIM];
static __device__ __half g_eh [(size_t)NH*SDIM*SDIM];
static __device__ __half g_xh [SDIM*EDIM];
static __device__ __half g_wh [(size_t)NOUT*EDIM];
static __device__ __half g_woh[(size_t)EDIM*EDIM];
static __device__ __half g_aoh[(size_t)SDIM*EDIM];
static __device__ __half g_qa [(size_t)NH*SDIM*KQ];
static __device__ __half g_kb [(size_t)NH*SDIM*KQ];
static __device__ __half g_vth[(size_t)NKV*DH*SDIM];

// ---------------- PTX helpers ----------------
__device__ __forceinline__ uint32_t smem_u32(const void* p) {
    uint32_t a;
    asm("{ .reg .u64 t; cvta.to.shared.u64 t, %1; cvt.u32.u64 %0, t; }" : "=r"(a) : "l"(p));
    return a;
}
__device__ __forceinline__ void cpa16(uint32_t d, const void* g) {
    asm volatile("cp.async.cg.shared.global [%0], [%1], 16;" :: "r"(d), "l"(g));
}
__device__ __forceinline__ void cp_commit() { asm volatile("cp.async.commit_group;" ::: "memory"); }
template<int N> __device__ __forceinline__ void cp_wait() {
    asm volatile("cp.async.wait_group %0;" :: "n"(N) : "memory");
}
__device__ __forceinline__ void ldm_x4(uint32_t& r0, uint32_t& r1, uint32_t& r2, uint32_t& r3,
                                       uint32_t addr) {
    asm volatile("ldmatrix.sync.aligned.m8n8.x4.shared.b16 {%0,%1,%2,%3}, [%4];"
                 : "=r"(r0), "=r"(r1), "=r"(r2), "=r"(r3) : "r"(addr));
}
__device__ __forceinline__ void mma_f16(float* d, const uint32_t* a, const uint32_t* b) {
    asm volatile("mma.sync.aligned.m16n8k16.row.col.f32.f16.f16.f32 "
                 "{%0,%1,%2,%3}, {%4,%5,%6,%7}, {%8,%9}, {%0,%1,%2,%3};"
                 : "+f"(d[0]), "+f"(d[1]), "+f"(d[2]), "+f"(d[3])
                 : "r"(a[0]), "r"(a[1]), "r"(a[2]), "r"(a[3]), "r"(b[0]), "r"(b[1]));
}
__device__ __forceinline__ void sbody1(const float* s, __half* dh, int i) {
    float2 v = ((const float2*)s)[i];
    __half h0 = __float2half_rn(v.x), h1 = __float2half_rn(v.y);
    ((uint32_t*)dh)[i] = (uint32_t)__half_as_ushort(h0)
                       | ((uint32_t)__half_as_ushort(h1) << 16);
}

// ---------------- merged split: x | Wq | Wk | Wv | Wrq | Wrk | Wo ----------
__global__ __launch_bounds__(256) void split_all(
    const float* __restrict__ x,  const float* __restrict__ wq,
    const float* __restrict__ wk, const float* __restrict__ wv,
    const float* __restrict__ wrq, const float* __restrict__ wrk,
    const float* __restrict__ wo)
{
    int i = blockIdx.x * 256 + threadIdx.x;
    const int E0 = 2097152, E1 = 4194304, E2 = 4718592, E3 = 5242880,
              E4 = 5636096, E5 = 6029312, E6 = 8126464;
    if      (i < E0) sbody1(x,   g_xh, i);
    else if (i < E1) sbody1(wq,  g_wh + (size_t)CQ  * EDIM, i - E0);
    else if (i < E2) sbody1(wk,  g_wh + (size_t)CK  * EDIM, i - E1);
    else if (i < E3) sbody1(wv,  g_wh + (size_t)CV  * EDIM, i - E2);
    else if (i < E4) sbody1(wrq, g_wh + (size_t)CRQ * EDIM, i - E3);
    else if (i < E5) sbody1(wrk, g_wh + (size_t)CRK * EDIM, i - E4);
    else if (i < E6) sbody1(wo,  g_woh, i - E5);
}

// ---------------- shared machinery ----------------
#define GEMM_PREAMBLE                                                           \
    extern __shared__ __align__(1024) char dsm[];                               \
    const uint32_t sb = smem_u32(dsm);                                          \
    const int tid = threadIdx.x;                                                \
    const int l = tid & 31, wid = tid >> 5;                                     \
    const int cch = tid & 7;                                                    \
    const int akh = (l >> 4);                                                   \
    const int bkh = (l >> 3) & 1;                                               \
    const int lsw = l & 7;

#define LOAD128(base, P, ld, step) do {                                         \
    const __half* G = (P) + (size_t)(step) * 64;                                \
    _Pragma("unroll")                                                           \
    for (int it = 0; it < 4; it++) {                                            \
        int row = (tid >> 3) + 32 * it;                                         \
        uint32_t sw = row * 128u + 16u * (cch ^ (row & 7));                     \
        cpa16((base) + sw, G + (size_t)row * (ld) + cch * 8);                   \
    } } while (0)

#define LOAD64(base, P, ld, step) do {                                          \
    const __half* G = (P) + (size_t)(step) * 64;                                \
    _Pragma("unroll")                                                           \
    for (int it = 0; it < 2; it++) {                                            \
        int row = (tid >> 3) + 32 * it;                                         \
        uint32_t sw = row * 128u + 16u * (cch ^ (row & 7));                     \
        cpa16((base) + sw, G + (size_t)row * (ld) + cch * 8);                   \
    } } while (0)

#define INNER_128(Ab, Bb)                                                       \
    _Pragma("unroll")                                                           \
    for (int kk = 0; kk < 4; kk++) {                                            \
        uint32_t af[4][4], bf[4][2];                                            \
        _Pragma("unroll")                                                       \
        for (int tm = 0; tm < 4; tm++)                                          \
            ldm_x4(af[tm][0], af[tm][1], af[tm][2], af[tm][3],                  \
                   (Ab) + (uint32_t)(ar + tm * 16) * 128u + 16u * (((kk << 1) + akh) ^ lsw)); \
        _Pragma("unroll")                                                       \
        for (int np = 0; np < 2; np++) {                                        \
            uint32_t r0, r1, r2, r3;                                            \
            ldm_x4(r0, r1, r2, r3,                                              \
                   (Bb) + (uint32_t)(br + np * 16) * 128u + 16u * (((kk << 1) + bkh) ^ lsw)); \
            bf[2*np][0] = r0; bf[2*np][1] = r1; bf[2*np+1][0] = r2; bf[2*np+1][1] = r3; \
        }                                                                       \
        _Pragma("unroll")                                                       \
        for (int tm = 0; tm < 4; tm++)                                          \
            _Pragma("unroll")                                                   \
            for (int tn = 0; tn < 4; tn++) mma_f16(acc[tm][tn], af[tm], bf[tn]); \
    }

// ---------------- single-product fp16 GEMM (proj / Wo) — round-14 config ----
// CTA 64x128; stage: A 8KB @0, B 16KB @8192; 2 stages, stride 24576 (48KB).
__global__ __launch_bounds__(256, 3) void gemm1(
    const __half* __restrict__ Ah, const __half* __restrict__ Bh,
    float* __restrict__ C, int ldc, int K)
{
    GEMM_PREAMBLE
    const int wm = wid & 1, wn = wid >> 1;
    const int m0 = blockIdx.y << 6, n0 = blockIdx.x << 7;
    const int steps = K >> 6;
    const __half* Ah_ = Ah + (size_t)m0 * K;
    const __half* Bh_ = Bh + (size_t)n0 * K;

    float acc[2][4][4];
#pragma unroll
    for (int i = 0; i < 2; i++)
#pragma unroll
        for (int j = 0; j < 4; j++)
#pragma unroll
            for (int r = 0; r < 4; r++) acc[i][j][r] = 0.f;

    const int ar = wm * 32 + (l & 7) + (l & 8);
    const int br = wn * 32 + (l & 7) + 8 * (l >> 4);

    LOAD64(sb, Ah_, K, 0);
    LOAD128(sb + 8192u, Bh_, K, 0);
    cp_commit();

    for (int s = 0; s < steps; s++) {
        cp_wait<0>();
        __syncthreads();
        if (s + 1 < steps) {
            uint32_t b2 = sb + ((s + 1) & 1) * 24576u;
            LOAD64(b2, Ah_, K, s + 1);
            LOAD128(b2 + 8192u, Bh_, K, s + 1);
            cp_commit();
        }
        const uint32_t Ast = sb + (s & 1) * 24576u;
        const uint32_t Bst = Ast + 8192u;
#pragma unroll
        for (int kk = 0; kk < 4; kk++) {
            uint32_t bf[4][2], af[2][4];
#pragma unroll
            for (int np = 0; np < 2; np++) {
                uint32_t r0, r1, r2, r3;
                ldm_x4(r0, r1, r2, r3,
                       Bst + (uint32_t)(br + np * 16) * 128u + 16u * (((kk << 1) + bkh) ^ lsw));
                bf[2*np][0] = r0; bf[2*np][1] = r1; bf[2*np+1][0] = r2; bf[2*np+1][1] = r3;
            }
#pragma unroll
            for (int tm = 0; tm < 2; tm++)
                ldm_x4(af[tm][0], af[tm][1], af[tm][2], af[tm][3],
                       Ast + (uint32_t)(ar + tm * 16) * 128u + 16u * (((kk << 1) + akh) ^ lsw));
#pragma unroll
            for (int tm = 0; tm < 2; tm++)
#pragma unroll
                for (int tn = 0; tn < 4; tn++) mma_f16(acc[tm][tn], af[tm], bf[tn]);
        }
    }
    const int er = m0 + wm * 32 + (l >> 2);
    const int ec = n0 + wn * 32 + 2 * (l & 3);
#pragma unroll
    for (int tm = 0; tm < 2; tm++)
#pragma unroll
        for (int tn = 0; tn < 4; tn++) {
            float* p0 = C + (size_t)(er + tm * 16) * ldc + ec + tn * 8;
            float* p1 = C + (size_t)(er + tm * 16 + 8) * ldc + ec + tn * 8;
            *(float2*)p0 = make_float2(acc[tm][tn][0], acc[tm][tn][1]);
            *(float2*)p1 = make_float2(acc[tm][tn][2], acc[tm][tn][3]);
        }
}

// ---------------- scores: mma (KQ=192) + exp/16 -> fp16 + row-sum atomics ---
__global__ __launch_bounds__(256) void scores_mma()
{
    GEMM_PREAMBLE
    const int wm = wid & 1, wn = wid >> 1;
    const int h = blockIdx.y, idx = blockIdx.x;
    int ti = (int)((sqrtf(8.f * idx + 1.f) - 1.f) * 0.5f);
    while ((ti + 1) * (ti + 2) / 2 <= idx) ti++;
    while (ti * (ti + 1) / 2 > idx) ti--;
    const int tj = idx - ti * (ti + 1) / 2;
    const int i0 = ti << 7, j0 = tj << 7;
    const __half* Ab_ = g_qa + ((size_t)h * SDIM + i0) * KQ;
    const __half* Bb_ = g_kb + ((size_t)h * SDIM + j0) * KQ;
    const int steps = KQ >> 6;

    float acc[4][4][4];
#pragma unroll
    for (int i = 0; i < 4; i++)
#pragma unroll
        for (int j = 0; j < 4; j++)
#pragma unroll
            for (int r = 0; r < 4; r++) acc[i][j][r] = 0.f;
    const int ar = wm * 64 + (l & 7) + (l & 8);
    const int br = wn * 32 + (l & 7) + 8 * (l >> 4);

    LOAD128(sb, Ab_, KQ, 0); LOAD128(sb + 16384u, Bb_, KQ, 0); cp_commit();
    LOAD128(sb + 32768u, Ab_, KQ, 1); LOAD128(sb + 49152u, Bb_, KQ, 1); cp_commit();

    for (int s = 0; s < steps; s++) {
        cp_wait<1>();
        __syncthreads();
        if (s + 2 < steps) {
            uint32_t b2 = sb + ((s + 2) % 3) * 32768u;
            LOAD128(b2, Ab_, KQ, s + 2); LOAD128(b2 + 16384u, Bb_, KQ, s + 2);
        }
        cp_commit();
        const uint32_t Ab = sb + (s % 3) * 32768u;
        const uint32_t Bb = Ab + 16384u;
        INNER_128(Ab, Bb)
    }
    const int er = i0 + wm * 64 + (l >> 2);
    const int ec = j0 + wn * 32 + 2 * (l & 3);
    float rsum[4][2];
#pragma unroll
    for (int tm = 0; tm < 4; tm++) { rsum[tm][0] = 0.f; rsum[tm][1] = 0.f; }
#pragma unroll
    for (int tm = 0; tm < 4; tm++)
#pragma unroll
        for (int tn = 0; tn < 4; tn++) {
            int r0 = er + tm * 16, r1 = r0 + 8, c = ec + tn * 8;
            float e00 = (c     <= r0) ? __expf(acc[tm][tn][0]) * 0.0625f : 0.f;
            float e01 = (c + 1 <= r0) ? __expf(acc[tm][tn][1]) * 0.0625f : 0.f;
            float e10 = (c     <= r1) ? __expf(acc[tm][tn][2]) * 0.0625f : 0.f;
            float e11 = (c + 1 <= r1) ? __expf(acc[tm][tn][3]) * 0.0625f : 0.f;
            __half2 v0; v0.x = __float2half_rn(e00); v0.y = __float2half_rn(e01);
            __half2 v1; v1.x = __float2half_rn(e10); v1.y = __float2half_rn(e11);
            *(__half2*)(g_eh + ((size_t)h * SDIM + r0) * SDIM + c) = v0;
            *(__half2*)(g_eh + ((size_t)h * SDIM + r1) * SDIM + c) = v1;
            rsum[tm][0] += e00 + e01;
            rsum[tm][1] += e10 + e11;
        }
#pragma unroll
    for (int tm = 0; tm < 4; tm++)
#pragma unroll
        for (int rr = 0; rr < 2; rr++) {
            float v = rsum[tm][rr];
            v += __shfl_xor_sync(0xffffffffu, v, 1);
            v += __shfl_xor_sync(0xffffffffu, v, 2);
            if ((l & 3) == 0)
                atomicAdd(&g_rs[h * SDIM + er + tm * 16 + rr * 8], v);
        }
}

// ---------------- AV: single-product GEMM over eh, normalize at end ----------
__global__ __launch_bounds__(256) void av_mma()
{
    GEMM_PREAMBLE
    const int wm = wid & 1, wn = wid >> 1;
    const int h = blockIdx.y;
    const __half* Vh_ = g_vth + (size_t)(h >> 2) * DH * SDIM;

    const int ar = wm * 32 + (l & 7) + (l & 8);
    const int br = wn * 32 + (l & 7) + 8 * (l >> 4);

    for (int half = 0; half < 2; half++) {
        const int mt = half ? 31 - (int)blockIdx.x : (int)blockIdx.x;
        const int m0 = mt << 6;
        const int steps = mt + 1;
        const __half* Ae_ = g_eh + ((size_t)h * SDIM + m0) * SDIM;

        float acc[2][4][4];
#pragma unroll
        for (int i = 0; i < 2; i++)
#pragma unroll
            for (int j = 0; j < 4; j++)
#pragma unroll
                for (int r = 0; r < 4; r++) acc[i][j][r] = 0.f;

        LOAD64(sb, Ae_, SDIM, 0);
        LOAD128(sb + 8192u, Vh_, SDIM, 0);
        cp_commit();

        for (int s = 0; s < steps; s++) {
            cp_wait<0>();
            __syncthreads();
            if (s + 1 < steps) {
                uint32_t b2 = sb + ((s + 1) & 1) * 24576u;
                LOAD64(b2, Ae_, SDIM, s + 1);
                LOAD128(b2 + 8192u, Vh_, SDIM, s + 1);
                cp_commit();
            }
            const uint32_t Ast = sb + (s & 1) * 24576u;
            const uint32_t Bst = Ast + 8192u;
#pragma unroll
            for (int kk = 0; kk < 4; kk++) {
                uint32_t bf[4][2], af[2][4];
#pragma unroll
                for (int np = 0; np < 2; np++) {
                    uint32_t r0, r1, r2, r3;
                    ldm_x4(r0, r1, r2, r3,
                           Bst + (uint32_t)(br + np * 16) * 128u + 16u * (((kk << 1) + bkh) ^ lsw));
                    bf[2*np][0] = r0; bf[2*np][1] = r1; bf[2*np+1][0] = r2; bf[2*np+1][1] = r3;
                }
#pragma unroll
                for (int tm = 0; tm < 2; tm++)
                    ldm_x4(af[tm][0], af[tm][1], af[tm][2], af[tm][3],
                           Ast + (uint32_t)(ar + tm * 16) * 128u + 16u * (((kk << 1) + akh) ^ lsw));
#pragma unroll
                for (int tm = 0; tm < 2; tm++)
#pragma unroll
                    for (int tn = 0; tn < 4; tn++) mma_f16(acc[tm][tn], af[tm], bf[tn]);
            }
        }
        const int er = m0 + wm * 32 + (l >> 2);
        const int ecl = wn * 32 + 2 * (l & 3);
#pragma unroll
        for (int tm = 0; tm < 2; tm++) {
            float ir0 = 1.f / g_rs[h * SDIM + er + tm * 16];
            float ir1 = 1.f / g_rs[h * SDIM + er + tm * 16 + 8];
#pragma unroll
            for (int tn = 0; tn < 4; tn++) {
                int c = h * DH + ecl + tn * 8;
                int r0 = er + tm * 16, r1 = r0 + 8;
                __half h00 = __float2half_rn(acc[tm][tn][0] * ir0);
                __half h01 = __float2half_rn(acc[tm][tn][1] * ir0);
                __half h10 = __float2half_rn(acc[tm][tn][2] * ir1);
                __half h11 = __float2half_rn(acc[tm][tn][3] * ir1);
                ((uint32_t*)g_aoh)[(size_t)r0 * (EDIM/2) + (c >> 1)] =
                    (uint32_t)__half_as_ushort(h00) | ((uint32_t)__half_as_ushort(h01) << 16);
                ((uint32_t*)g_aoh)[(size_t)r1 * (EDIM/2) + (c >> 1)] =
                    (uint32_t)__half_as_ushort(h10) | ((uint32_t)__half_as_ushort(h11) << 16);
            }
        }
        __syncthreads();
    }
}

// ---------------- merged RMSNorm + RoPE fill: qa (y<16) / kb (y>=16) --------
__global__ __launch_bounds__(128) void norm_fill(
    const float* __restrict__ qw, const float* __restrict__ kw,
    const float* __restrict__ gscale)
{
    const int s = blockIdx.x, y = blockIdx.y, d = threadIdx.x;
    const bool isQ = (y < NH);
    const int hq = y, kvh = y - NH;
    const float* w = isQ ? qw : kw;
    const int col = isQ ? (CQ + hq * DH) : (CK + kvh * DH);
    float v = g_pr[(size_t)s * NOUT + col + d];
    float ss = v * v;
#pragma unroll
    for (int o = 16; o; o >>= 1) ss += __shfl_xor_sync(0xffffffffu, ss, o);
    __shared__ float r4[4];
    __shared__ float sh[DH];
    if ((d & 31) == 0) r4[d >> 5] = ss;
    __syncthreads();
    float nv = v * rsqrtf((r4[0]+r4[1]+r4[2]+r4[3]) * (1.f / DH) + 1e-6f) * w[d];
    sh[d] = nv;
    __syncthreads();
    const int dm = d & 63;
    float f = 1.f / powf(10000.f, (float)(2 * dm) * (1.f / DH));
    float cs, sn; sincosf((float)s * f, &sn, &cs);
    float rot = (d < 64) ? -sh[d + 64] : sh[d - 64];
    float rv = nv * cs + rot * sn;

    if (isQ) {
        __half* row = g_qa + ((size_t)hq * SDIM + s) * KQ;
        row[d] = __float2half_rn(rv * 0.08838834764831845f);
        if (d < 32) {
            float bv = 0.f;
            if (hq < NHG) bv = gscale[hq] * (hq < NSYM ? 0.5f : 1.f)
                             * g_pr[(size_t)s * NOUT + CRQ + hq * RDIM + d];
            row[128 + d] = __float2half_rn(bv);
        } else if (d < 64) {
            int r = d - 32;
            float bv = 0.f;
            if (hq < NSYM) bv = gscale[hq] * 0.5f * g_pr[(size_t)s * NOUT + CRK + hq * RDIM + r];
            row[160 + r] = __float2half_rn(bv);
        }
    } else {
        __half kh = __float2half_rn(rv);
#pragma unroll
        for (int e = 0; e < 4; e++) {
            int h = kvh * 4 + e;
            __half* row = g_kb + ((size_t)h * SDIM + s) * KQ;
            row[d] = kh;
            if (d < 32) {
                float bv = (h < NHG) ? g_pr[(size_t)s * NOUT + CRK + h * RDIM + d] : 0.f;
                row[128 + d] = __float2half_rn(bv);
            } else if (d < 64) {
                int r = d - 32;
                float bv = (h < NSYM) ? g_pr[(size_t)s * NOUT + CRQ + h * RDIM + r] : 0.f;
                row[160 + r] = __float2half_rn(bv);
            }
        }
    }
}

// ---------------- fill vth (smem transpose, fp16 single) ----------------
__global__ __launch_bounds__(128) void fill_vh()
{
    __shared__ float sm[64][129];
    const int jb = blockIdx.x, kvh = blockIdx.y;
    const int tid = threadIdx.x;
    for (int jj = 0; jj < 64; jj++)
        sm[jj][tid] = g_pr[(size_t)(jb * 64 + jj) * NOUT + CV + kvh * DH + tid];
    __syncthreads();
    const int w = tid >> 5, ln = tid & 31;
    for (int d = w; d < DH; d += 4) {
        __half h0 = __float2half_rn(sm[2*ln][d]);
        __half h1 = __float2half_rn(sm[2*ln+1][d]);
        uint32_t* oh = (uint32_t*)(g_vth + (size_t)(kvh * DH + d) * SDIM + jb * 64);
        oh[ln] = (uint32_t)__half_as_ushort(h0) | ((uint32_t)__half_as_ushort(h1) << 16);
    }
}

// ---------------- Host ----------------
extern "C" void kernel_launch(void* const* d_in, const int* in_sizes, int n_in,
                              void* d_out, int out_size)
{
    const float* x   = (const float*)d_in[0];
    const float* Wq  = (const float*)d_in[1];
    const float* Wk  = (const float*)d_in[2];
    const float* Wv  = (const float*)d_in[3];
    const float* Wo  = (const float*)d_in[4];
    const float* qnw = (const float*)d_in[5];
    const float* knw = (const float*)d_in[6];
    const float* Wrq = (const float*)d_in[7];
    const float* Wrk = (const float*)d_in[8];
    const float* gsc = (const float*)d_in[9];
    float* out = (float*)d_out;

    float *pr, *rs;
    __half *xh, *wh, *woh, *aoh;
    cudaGetSymbolAddress((void**)&pr,  g_pr);
    cudaGetSymbolAddress((void**)&rs,  g_rs);
    cudaGetSymbolAddress((void**)&xh,  g_xh);
    cudaGetSymbolAddress((void**)&wh,  g_wh);
    cudaGetSymbolAddress((void**)&woh, g_woh);
    cudaGetSymbolAddress((void**)&aoh, g_aoh);

    cudaFuncSetAttribute(gemm1,      cudaFuncAttributeMaxDynamicSharedMemorySize, 49152);
    cudaFuncSetAttribute(scores_mma, cudaFuncAttributeMaxDynamicSharedMemorySize, 98304);
    cudaFuncSetAttribute(av_mma,     cudaFuncAttributeMaxDynamicSharedMemorySize, 49152);

    split_all<<<31744, 256>>>(x, Wq, Wk, Wv, Wrq, Wrk, Wo);

    // merged projection GEMM (round-14 gemm1: CTA 64x128, warp 32x32, occ 3)
    gemm1<<<dim3(NOUT/128, SDIM/64), 256, 49152>>>(xh, wh, pr, NOUT, EDIM);

    cudaMemsetAsync(rs, 0, NH * SDIM * sizeof(float));

    norm_fill<<<dim3(SDIM, NH + NKV), 128>>>(qnw, knw, gsc);
    fill_vh<<<dim3(SDIM/64, NKV), 128>>>();

    scores_mma<<<dim3(136, NH), 256, 98304>>>();
    av_mma<<<dim3(16, NH), 256, 49152>>>();

    gemm1<<<dim3(EDIM/128, SDIM/64), 256, 49152>>>(aoh, woh, out, EDIM, EDIM);
}